// round 1
// baseline (speedup 1.0000x reference)
#include <cuda_runtime.h>
#include <stdint.h>

#define N_   32
#define H_   56
#define W_   56
#define C_   256
#define HP   58
#define WP   58
#define COUT 256
#define NTAP 9
#define NWRD 72   /* 9 taps * 8 channel-groups of 32 */

// Scratch (device globals — no allocation allowed)
__device__ uint32_t g_kbits[NWRD * COUT];          // [word][cout] packed sign bits of kernel
__device__ float    g_alpha[COUT];                 // mean |k| per cout
__device__ uint32_t g_xbits[N_ * HP * WP * 8];     // packed sign bits of padded x, 8 words/pixel
__device__ float    g_beta [N_ * HP * WP];         // sum |x| over channels per padded pixel

// ---------------------------------------------------------------------------
// Pack kernel sign bits: bit b of word (tap, g) for output co <-> cin = g*32+b
// kernel layout HWIO: k[(tap*256 + cin)*256 + co]
__global__ void prep_kbits(const float* __restrict__ k) {
    int w  = blockIdx.x;        // 0..71
    int co = threadIdx.x;       // 0..255
    int tap = w >> 3, g = w & 7;
    const float* base = k + ((size_t)tap * C_ + g * 32) * COUT + co;
    uint32_t bits = 0;
#pragma unroll
    for (int b = 0; b < 32; b++) {
        if (base[(size_t)b * COUT] > 0.f) bits |= (1u << b);
    }
    g_kbits[w * COUT + co] = bits;
}

// alpha[co] = mean(|k|) over 3*3*256 = 2304 elements. One block per cout.
__global__ void prep_alpha(const float* __restrict__ k) {
    __shared__ float red[256];
    int co = blockIdx.x;
    float s = 0.f;
    for (int i = threadIdx.x; i < NTAP * C_; i += 256)
        s += fabsf(k[(size_t)i * COUT + co]);
    red[threadIdx.x] = s;
    __syncthreads();
    for (int o = 128; o; o >>= 1) {
        if (threadIdx.x < o) red[threadIdx.x] += red[threadIdx.x + o];
        __syncthreads();
    }
    if (threadIdx.x == 0) g_alpha[co] = red[0] * (1.f / (NTAP * C_));
}

// ---------------------------------------------------------------------------
// Pack input sign bits + per-pixel sum|x| over channels, into padded layout.
// One warp per padded pixel; boundary ring -> bits 0 (sign -1) and beta 0.
__global__ void prep_x(const float* __restrict__ x) {
    int pix  = blockIdx.x * 8 + (threadIdx.x >> 5);
    int lane = threadIdx.x & 31;
    if (pix >= N_ * HP * WP) return;
    int n  = pix / (HP * WP);
    int r  = pix % (HP * WP);
    int hp = r / WP, wp = r % WP;
    if (hp >= 1 && hp <= H_ && wp >= 1 && wp <= W_) {
        const float* xp = x + (((size_t)n * H_ + (hp - 1)) * W_ + (wp - 1)) * C_;
        float asum = 0.f;
#pragma unroll
        for (int j = 0; j < 8; j++) {
            float v = xp[j * 32 + lane];
            unsigned m = __ballot_sync(0xffffffffu, v > 0.f);
            if (lane == j) g_xbits[(size_t)pix * 8 + j] = m;
            asum += fabsf(v);
        }
#pragma unroll
        for (int o = 16; o; o >>= 1) asum += __shfl_xor_sync(0xffffffffu, asum, o);
        if (lane == 0) g_beta[pix] = asum;
    } else {
        if (lane < 8) g_xbits[(size_t)pix * 8 + lane] = 0u;
        if (lane == 0) g_beta[pix] = 0.f;
    }
}

// ---------------------------------------------------------------------------
// Main XNOR-popcount conv. One warp computes one pixel x all 256 couts
// (8 couts per lane, cout = j*32 + lane). Kernel bits staged once in SMEM
// per (persistent) block; grid-stride over pixels.
__global__ void __launch_bounds__(256) binconv_main(
        const float* __restrict__ bias, float* __restrict__ out) {
    extern __shared__ uint32_t smem[];
    uint32_t* s_k     = smem;                               // NWRD*COUT words
    float*    s_alpha = (float*)(smem + NWRD * COUT);       // 256
    float*    s_bias  = s_alpha + COUT;                     // 256

    {   // cooperative vectorized smem fill
        const uint4* src = (const uint4*)g_kbits;
        uint4*       dst = (uint4*)s_k;
        for (int i = threadIdx.x; i < (NWRD * COUT) / 4; i += 256) dst[i] = src[i];
        if (threadIdx.x < COUT) {
            s_alpha[threadIdx.x] = g_alpha[threadIdx.x];
            s_bias [threadIdx.x] = bias[threadIdx.x];
        }
    }
    __syncthreads();

    const int warp = threadIdx.x >> 5;
    const int lane = threadIdx.x & 31;
    const int NPIX = N_ * H_ * W_;

    for (int pix = blockIdx.x * 8 + warp; pix < NPIX; pix += gridDim.x * 8) {
        int n = pix / (H_ * W_);
        int r = pix % (H_ * W_);
        int h = r / W_, w = r % W_;

        uint32_t acc[8] = {0, 0, 0, 0, 0, 0, 0, 0};
        float ksum = 0.f;
#pragma unroll
        for (int kh = 0; kh < 3; kh++) {
#pragma unroll
            for (int kw = 0; kw < 3; kw++) {
                const int tap  = kh * 3 + kw;
                const int ppix = ((n * HP) + h + kh) * WP + (w + kw);
                const uint4* xp = (const uint4*)&g_xbits[(size_t)ppix * 8];
                uint4 x0 = xp[0];
                uint4 x1 = xp[1];
                ksum += g_beta[ppix];
                uint32_t xw[8] = {x0.x, x0.y, x0.z, x0.w, x1.x, x1.y, x1.z, x1.w};
#pragma unroll
                for (int g = 0; g < 8; g++) {
                    const uint32_t* kp = &s_k[(tap * 8 + g) * COUT + lane];
                    const uint32_t xv = xw[g];
#pragma unroll
                    for (int j = 0; j < 8; j++)
                        acc[j] += __popc(xv ^ kp[j * 32]);
                }
            }
        }

        // out = dot * (K * alpha) + bias,  dot = 2304 - 2*xor_popc, K = ksum/2304
        const float kscale = ksum * (1.f / 2304.f);
        float* op = out + (size_t)pix * COUT;
#pragma unroll
        for (int j = 0; j < 8; j++) {
            int   co  = j * 32 + lane;
            float dot = 2304.f - 2.f * (float)acc[j];
            op[co] = dot * (kscale * s_alpha[co]) + s_bias[co];
        }
    }
}

// ---------------------------------------------------------------------------
extern "C" void kernel_launch(void* const* d_in, const int* in_sizes, int n_in,
                              void* d_out, int out_size) {
    (void)in_sizes; (void)n_in; (void)out_size;
    const float* x    = (const float*)d_in[0];
    const float* kern = (const float*)d_in[1];
    const float* bias = (const float*)d_in[2];
    float*       out  = (float*)d_out;

    prep_kbits<<<NWRD, 256>>>(kern);
    prep_alpha<<<COUT, 256>>>(kern);

    const int npixp = N_ * HP * WP;           // 107648, divisible by 8
    prep_x<<<npixp / 8, 256>>>(x);

    const size_t smem_bytes = (size_t)NWRD * COUT * 4 + 2 * COUT * 4;  // 75776
    cudaFuncSetAttribute(binconv_main, cudaFuncAttributeMaxDynamicSharedMemorySize,
                         (int)smem_bytes);
    binconv_main<<<444, 256, smem_bytes>>>(bias, out);
}

// round 2
// speedup vs baseline: 4.1885x; 4.1885x over previous
#include <cuda_runtime.h>
#include <stdint.h>

#define N_   32
#define H_   56
#define W_   56
#define C_   256
#define HP   58          /* padded height */
#define WP   58          /* padded width (logical) */
#define WPS  64          /* padded row stride in words (aligned) */
#define COUT 256
#define NTAP 9
#define NWRD 72          /* 9 taps * 8 cin-groups */
#define NXP  (N_ * HP * WPS)        /* words per bit-plane = 118784 */
#define NTILES (N_ * H_ * 7)        /* 8-pixel tiles = 12544 */

// Scratch (device globals — no allocation allowed)
__device__ uint32_t g_kbits[NWRD * COUT];   // [tap*8+gc][cout] packed kernel sign bits
__device__ float    g_alpha[COUT];          // mean |k| per cout
__device__ uint32_t g_xbt [8 * NXP];        // PLANAR packed x sign bits: [gc][padded pix]
__device__ float    g_betap[NXP];           // sum |x| over channels per padded pixel

// ---------------------------------------------------------------------------
// Pack kernel sign bits: bit b of word (tap, gc) for cout co <-> cin = gc*32+b
// kernel layout HWIO: k[(tap*256 + cin)*256 + co]
__global__ void prep_kbits(const float* __restrict__ k) {
    int w  = blockIdx.x;        // 0..71
    int co = threadIdx.x;       // 0..255
    int tap = w >> 3, g = w & 7;
    const float* base = k + ((size_t)tap * C_ + g * 32) * COUT + co;
    uint32_t bits = 0;
#pragma unroll
    for (int b = 0; b < 32; b++)
        if (base[(size_t)b * COUT] > 0.f) bits |= (1u << b);
    g_kbits[w * COUT + co] = bits;
}

// alpha[co] = mean(|k|) over 2304 elements. One block per cout.
__global__ void prep_alpha(const float* __restrict__ k) {
    __shared__ float red[256];
    int co = blockIdx.x;
    float s = 0.f;
    for (int i = threadIdx.x; i < NTAP * C_; i += 256)
        s += fabsf(k[(size_t)i * COUT + co]);
    red[threadIdx.x] = s;
    __syncthreads();
    for (int o = 128; o; o >>= 1) {
        if (threadIdx.x < o) red[threadIdx.x] += red[threadIdx.x + o];
        __syncthreads();
    }
    if (threadIdx.x == 0) g_alpha[co] = red[0] * (1.f / (NTAP * C_));
}

// ---------------------------------------------------------------------------
// Pack input sign bits (planar layout) + per-pixel sum|x|.
// One warp per padded pixel; border ring -> bits 0 (sign -1) and beta 0.
__global__ void prep_x(const float* __restrict__ x) {
    int pix  = blockIdx.x * 8 + (threadIdx.x >> 5);
    int lane = threadIdx.x & 31;
    if (pix >= N_ * HP * WP) return;
    int n  = pix / (HP * WP);
    int r  = pix % (HP * WP);
    int hp = r / WP, wp = r % WP;
    int ppos = (n * HP + hp) * WPS + wp;
    if (hp >= 1 && hp <= H_ && wp >= 1 && wp <= W_) {
        const float* xp = x + (((size_t)n * H_ + (hp - 1)) * W_ + (wp - 1)) * C_;
        float asum = 0.f;
        uint32_t bm[8];
#pragma unroll
        for (int j = 0; j < 8; j++) {
            float v = xp[j * 32 + lane];
            bm[j] = __ballot_sync(0xffffffffu, v > 0.f);
            asum += fabsf(v);
        }
#pragma unroll
        for (int o = 16; o; o >>= 1) asum += __shfl_xor_sync(0xffffffffu, asum, o);
#pragma unroll
        for (int j = 0; j < 8; j++)
            if (lane == j) g_xbt[(size_t)j * NXP + ppos] = bm[j];
        if (lane == 0) g_betap[ppos] = asum;
    } else {
        if (lane < 8) g_xbt[(size_t)lane * NXP + ppos] = 0u;
        if (lane == 0) g_betap[ppos] = 0.f;
    }
}

// ---------------------------------------------------------------------------
// Main XNOR-popcount conv.
// Warp = 8 output pixels (a row segment) x 64 couts (2 per lane).
// Block = 256 thr = 8 warps: sub = warp>>2 selects one of 2 tiles,
// cg = warp&3 selects the 64-cout group. Kernel bits staged once in SMEM
// (72KB) per persistent block; grid-stride over tile pairs.
__global__ void __launch_bounds__(256) binconv_main(
        const float* __restrict__ bias, float* __restrict__ out) {
    extern __shared__ uint32_t s_k[];   // NWRD * COUT words = 72KB

    {   // cooperative vectorized smem fill
        const uint4* src = (const uint4*)g_kbits;
        uint4*       dst = (uint4*)s_k;
        for (int i = threadIdx.x; i < (NWRD * COUT) / 4; i += 256) dst[i] = src[i];
    }
    __syncthreads();

    const int warp = threadIdx.x >> 5;
    const int lane = threadIdx.x & 31;
    const int sub  = warp >> 2;     // 0/1: which tile of the pair
    const int cg   = warp & 3;      // cout group (64 couts)
    const int co0  = cg * 64 + 2 * lane;

    const float2 al = *(const float2*)(g_alpha + co0);
    const float2 bi = *(const float2*)(bias + co0);

    for (int bt = blockIdx.x; bt < NTILES / 2; bt += gridDim.x) {
        int t  = bt * 2 + sub;
        int tw = t % 7;
        int tr = t / 7;
        int th = tr % H_;
        int n  = tr / H_;
        int rb = (n * HP + th) * WPS + tw * 8;   // padded base: row th, col w0

        uint32_t acc0[8] = {0,0,0,0,0,0,0,0};
        uint32_t acc1[8] = {0,0,0,0,0,0,0,0};

#pragma unroll 2
        for (int gc = 0; gc < 8; gc++) {
            const uint32_t* xplane = g_xbt + (size_t)gc * NXP + rb;
#pragma unroll
            for (int kh = 0; kh < 3; kh++) {
                const uint4* xr = (const uint4*)(xplane + kh * WPS);
                uint4 q0 = xr[0], q1 = xr[1], q2 = xr[2];
                uint32_t xw[12] = {q0.x, q0.y, q0.z, q0.w,
                                   q1.x, q1.y, q1.z, q1.w,
                                   q2.x, q2.y, q2.z, q2.w};
#pragma unroll
                for (int kw = 0; kw < 3; kw++) {
                    const uint2* kp =
                        (const uint2*)(s_k + ((kh * 3 + kw) * 8 + gc) * COUT + cg * 64);
                    uint2 kv = kp[lane];
#pragma unroll
                    for (int p = 0; p < 8; p++) {
                        acc0[p] += __popc(xw[p + kw] ^ kv.x);
                        acc1[p] += __popc(xw[p + kw] ^ kv.y);
                    }
                }
            }
        }

        // Epilogue: ksum[p] = 3x3 window sum of beta; out = dot*K*alpha + bias
        const float4* br0 = (const float4*)(g_betap + rb);
        const float4* br1 = (const float4*)(g_betap + rb + WPS);
        const float4* br2 = (const float4*)(g_betap + rb + 2 * WPS);
        float4 a0 = br0[0], a1 = br0[1], a2 = br0[2];
        float4 b0 = br1[0], b1 = br1[1], b2 = br1[2];
        float4 c0 = br2[0], c1 = br2[1], c2 = br2[2];
        float rs[10];
        rs[0] = a0.x + b0.x + c0.x;  rs[1] = a0.y + b0.y + c0.y;
        rs[2] = a0.z + b0.z + c0.z;  rs[3] = a0.w + b0.w + c0.w;
        rs[4] = a1.x + b1.x + c1.x;  rs[5] = a1.y + b1.y + c1.y;
        rs[6] = a1.z + b1.z + c1.z;  rs[7] = a1.w + b1.w + c1.w;
        rs[8] = a2.x + b2.x + c2.x;  rs[9] = a2.y + b2.y + c2.y;

        // linear out pixel index = t*8 + p  (since W_ = 7 tiles * 8)
        float* op = out + (size_t)t * 8 * COUT + co0;
#pragma unroll
        for (int p = 0; p < 8; p++) {
            float ks = (rs[p] + rs[p + 1] + rs[p + 2]) * (1.f / 2304.f);
            float t0 = ks * al.x;
            float t1 = ks * al.y;
            float d0 = 2304.f - 2.f * (float)acc0[p];
            float d1 = 2304.f - 2.f * (float)acc1[p];
            float2 o;
            o.x = d0 * t0 + bi.x;
            o.y = d1 * t1 + bi.y;
            *(float2*)(op + (size_t)p * COUT) = o;
        }
    }
}

// ---------------------------------------------------------------------------
extern "C" void kernel_launch(void* const* d_in, const int* in_sizes, int n_in,
                              void* d_out, int out_size) {
    (void)in_sizes; (void)n_in; (void)out_size;
    const float* x    = (const float*)d_in[0];
    const float* kern = (const float*)d_in[1];
    const float* bias = (const float*)d_in[2];
    float*       out  = (float*)d_out;

    prep_kbits<<<NWRD, 256>>>(kern);
    prep_alpha<<<COUT, 256>>>(kern);

    const int npixp = N_ * HP * WP;           // 107648, divisible by 8
    prep_x<<<npixp / 8, 256>>>(x);

    const size_t smem_bytes = (size_t)NWRD * COUT * 4;   // 73728
    cudaFuncSetAttribute(binconv_main, cudaFuncAttributeMaxDynamicSharedMemorySize,
                         (int)smem_bytes);
    binconv_main<<<444, 256, smem_bytes>>>(bias, out);
}

// round 3
// speedup vs baseline: 4.3824x; 1.0463x over previous
#include <cuda_runtime.h>
#include <stdint.h>

#define N_   32
#define H_   56
#define W_   56
#define C_   256
#define HP   58          /* padded height */
#define WP   58          /* padded width (logical) */
#define WPS  64          /* padded row stride in words (aligned) */
#define COUT 256
#define NTAP 9
#define NWRD 72          /* 9 taps * 8 cin-groups */
#define NXP  (N_ * HP * WPS)        /* words per bit-plane = 118784 */
#define NTILES (N_ * H_ * 7)        /* 8-pixel tiles = 12544 */
#define NGRP  (NTILES / 8)          /* warp-groups of 8 tiles = 1568 */

// Scratch (device globals — no allocation allowed)
__device__ uint32_t g_kbits[NWRD * COUT];   // [tap*8+gc][cout] packed kernel sign bits
__device__ float    g_kpart[NWRD * COUT];   // partial |k| sums
__device__ float    g_alpha[COUT];          // mean |k| per cout
__device__ uint32_t g_xbt [8 * NXP];        // PLANAR packed x sign bits: [gc][padded pix]
__device__ float    g_betap[NXP];           // sum |x| over channels per padded pixel

// ---------------------------------------------------------------------------
// Coalesced kernel prep: block w handles cin rows [w*32, w*32+32) of the
// (2304 x 256) HWIO kernel matrix. Those 32 rows are exactly the bits of
// kbits word w (tap = w>>3, cin group = w&7). Also accumulates |k| partials.
__global__ void prep_k1(const float* __restrict__ k) {
    int w  = blockIdx.x;        // 0..71
    int co = threadIdx.x;       // 0..255
    const float* base = k + (size_t)w * 32 * COUT + co;
    uint32_t bits = 0;
    float s = 0.f;
#pragma unroll
    for (int b = 0; b < 32; b++) {
        float v = base[(size_t)b * COUT];
        if (v > 0.f) bits |= (1u << b);
        s += fabsf(v);
    }
    g_kbits[w * COUT + co] = bits;
    g_kpart[w * COUT + co] = s;
}

__global__ void prep_k2() {
    int co = threadIdx.x;
    float s = 0.f;
#pragma unroll
    for (int w = 0; w < NWRD; w++) s += g_kpart[w * COUT + co];
    g_alpha[co] = s * (1.f / (NTAP * C_));
}

// ---------------------------------------------------------------------------
// Pack input sign bits (planar layout) + per-pixel sum|x|.
// One warp per padded pixel; border ring -> bits 0 (sign -1) and beta 0.
__global__ void prep_x(const float* __restrict__ x) {
    int pix  = blockIdx.x * 8 + (threadIdx.x >> 5);
    int lane = threadIdx.x & 31;
    if (pix >= N_ * HP * WP) return;
    int n  = pix / (HP * WP);
    int r  = pix % (HP * WP);
    int hp = r / WP, wp = r % WP;
    int ppos = (n * HP + hp) * WPS + wp;
    if (hp >= 1 && hp <= H_ && wp >= 1 && wp <= W_) {
        const float* xp = x + (((size_t)n * H_ + (hp - 1)) * W_ + (wp - 1)) * C_;
        float asum = 0.f;
        uint32_t bm[8];
#pragma unroll
        for (int j = 0; j < 8; j++) {
            float v = xp[j * 32 + lane];
            bm[j] = __ballot_sync(0xffffffffu, v > 0.f);
            asum += fabsf(v);
        }
#pragma unroll
        for (int o = 16; o; o >>= 1) asum += __shfl_xor_sync(0xffffffffu, asum, o);
#pragma unroll
        for (int j = 0; j < 8; j++)
            if (lane == j) g_xbt[(size_t)j * NXP + ppos] = bm[j];
        if (lane == 0) g_betap[ppos] = asum;
    } else {
        if (lane < 8) g_xbt[(size_t)lane * NXP + ppos] = 0u;
        if (lane == 0) g_betap[ppos] = 0.f;
    }
}

// ---------------------------------------------------------------------------
// Main XNOR-popcount conv.
// blockIdx.y = cout-group cg (64 couts). All 8 warps of a block share cg, so
// SMEM holds only the 18KB kernel-bit slice -> ~5 CTAs/SM.
// Warp = 8 output pixels x 64 couts (2 per lane, packed 16-bit accumulators).
__global__ void __launch_bounds__(256, 5) binconv_main(
        const float* __restrict__ bias, float* __restrict__ out) {
    extern __shared__ uint32_t s_k[];   // NWRD * 64 words = 18KB slice

    const int cg = blockIdx.y;
    {   // cooperative vectorized smem fill of this cg's slice
        const uint4* src = (const uint4*)g_kbits;
        uint4*       dst = (uint4*)s_k;
        for (int m = threadIdx.x; m < NWRD * 16; m += 256) {
            int w = m >> 4, j = m & 15;
            dst[m] = src[w * 64 + cg * 16 + j];
        }
    }
    __syncthreads();

    const int warp = threadIdx.x >> 5;
    const int lane = threadIdx.x & 31;
    const int co0  = cg * 64 + 2 * lane;

    const float2 al = *(const float2*)(g_alpha + co0);
    const float2 bi = *(const float2*)(bias + co0);

    for (int grp = blockIdx.x; grp < NGRP; grp += gridDim.x) {
        int t  = grp * 8 + warp;
        int tw = t % 7;
        int tr = t / 7;
        int th = tr % H_;
        int n  = tr / H_;
        int rb = (n * HP + th) * WPS + tw * 8;   // padded base: row th, col tw*8

        uint32_t acc[8] = {0,0,0,0,0,0,0,0};     // lo16: co0, hi16: co0+1

#pragma unroll 2
        for (int gc = 0; gc < 8; gc++) {
            const uint32_t* xplane = g_xbt + (size_t)gc * NXP + rb;
#pragma unroll
            for (int kh = 0; kh < 3; kh++) {
                const uint4* xr = (const uint4*)(xplane + kh * WPS);
                uint4 q0 = xr[0], q1 = xr[1], q2 = xr[2];
                uint32_t xw[12] = {q0.x, q0.y, q0.z, q0.w,
                                   q1.x, q1.y, q1.z, q1.w,
                                   q2.x, q2.y, q2.z, q2.w};
                const uint2* k0 = (const uint2*)(s_k + ((kh * 3 + 0) * 8 + gc) * 64);
                const uint2* k1 = (const uint2*)(s_k + ((kh * 3 + 1) * 8 + gc) * 64);
                const uint2* k2 = (const uint2*)(s_k + ((kh * 3 + 2) * 8 + gc) * 64);
                uint2 kv0 = k0[lane], kv1 = k1[lane], kv2 = k2[lane];
#pragma unroll
                for (int p = 0; p < 8; p++) {
                    uint32_t s;
                    s  = (uint32_t)__popc(xw[p    ] ^ kv0.x)
                       + ((uint32_t)__popc(xw[p    ] ^ kv0.y) << 16);
                    s += (uint32_t)__popc(xw[p + 1] ^ kv1.x)
                       + ((uint32_t)__popc(xw[p + 1] ^ kv1.y) << 16);
                    s += (uint32_t)__popc(xw[p + 2] ^ kv2.x)
                       + ((uint32_t)__popc(xw[p + 2] ^ kv2.y) << 16);
                    acc[p] += s;
                }
            }
        }

        // Epilogue: ksum[p] = 3x3 window sum of beta; out = dot*K*alpha + bias
        const float* bp = g_betap + rb;
        float rs[10];
        {
            float4 a = *(const float4*)(bp);
            float4 b = *(const float4*)(bp + WPS);
            float4 c = *(const float4*)(bp + 2 * WPS);
            rs[0] = a.x + b.x + c.x;  rs[1] = a.y + b.y + c.y;
            rs[2] = a.z + b.z + c.z;  rs[3] = a.w + b.w + c.w;
        }
        {
            float4 a = *(const float4*)(bp + 4);
            float4 b = *(const float4*)(bp + WPS + 4);
            float4 c = *(const float4*)(bp + 2 * WPS + 4);
            rs[4] = a.x + b.x + c.x;  rs[5] = a.y + b.y + c.y;
            rs[6] = a.z + b.z + c.z;  rs[7] = a.w + b.w + c.w;
        }
        {
            float2 a = *(const float2*)(bp + 8);
            float2 b = *(const float2*)(bp + WPS + 8);
            float2 c = *(const float2*)(bp + 2 * WPS + 8);
            rs[8] = a.x + b.x + c.x;  rs[9] = a.y + b.y + c.y;
        }

        // linear out pixel index = t*8 + p  (W_ = 7 tiles * 8)
        float* op = out + (size_t)t * 8 * COUT + co0;
#pragma unroll
        for (int p = 0; p < 8; p++) {
            float ks = (rs[p] + rs[p + 1] + rs[p + 2]) * (1.f / 2304.f);
            float d0 = 2304.f - 2.f * (float)(acc[p] & 0xFFFFu);
            float d1 = 2304.f - 2.f * (float)(acc[p] >> 16);
            float2 o;
            o.x = d0 * (ks * al.x) + bi.x;
            o.y = d1 * (ks * al.y) + bi.y;
            *(float2*)(op + (size_t)p * COUT) = o;
        }
    }
}

// ---------------------------------------------------------------------------
extern "C" void kernel_launch(void* const* d_in, const int* in_sizes, int n_in,
                              void* d_out, int out_size) {
    (void)in_sizes; (void)n_in; (void)out_size;
    const float* x    = (const float*)d_in[0];
    const float* kern = (const float*)d_in[1];
    const float* bias = (const float*)d_in[2];
    float*       out  = (float*)d_out;

    prep_k1<<<NWRD, 256>>>(kern);
    prep_k2<<<1, 256>>>();

    const int npixp = N_ * HP * WP;           // 107648, divisible by 8
    prep_x<<<npixp / 8, 256>>>(x);

    const size_t smem_bytes = (size_t)NWRD * 64 * 4;   // 18432
    dim3 grid(185, 4);
    binconv_main<<<grid, 256, smem_bytes>>>(bias, out);
}